// round 12
// baseline (speedup 1.0000x reference)
#include <cuda_runtime.h>
#include <cuda_bf16.h>
#include <cstdint>

#define TT 2048
#define EE 1024
#define HH 16
#define DD 64
#define HD 1024
#define LOG2E 1.4426950408889634f

// ---------------- fp32 scratch ----------------
__device__ __align__(16) float g_q[TT * HD];
__device__ __align__(16) float g_k[TT * HD];
__device__ __align__(16) float g_v[TT * HD];
__device__ __align__(16) float g_rv[TT * HD];
__device__ __align__(16) float g_echo[TT * EE];
__device__ __align__(16) float g_r[HH * TT];
__device__ __align__(16) float g_sc[TT];
__device__ __align__(16) float g_o1[TT * HD];
__device__ __align__(16) float g_o2[TT * HD];
__device__ __align__(16) float g_o3a[TT * EE];
__device__ __align__(16) float g_o3b[TT * EE];
__device__ __align__(16) float g_f0[TT * EE];
__device__ __align__(16) float g_f1[TT * EE];

// ---------------- bf16 triple-split scratch ----------------
__device__ __align__(16) __nv_bfloat16 g_x3[TT * 3072];
__device__ __align__(16) __nv_bfloat16 g_w6[6144 * 3072];
__device__ __align__(16) __nv_bfloat16 g_echoT3[1024 * 6144];
__device__ __align__(16) __nv_bfloat16 g_P3[TT * 6144];
__device__ __align__(16) __nv_bfloat16 g_comb3[TT * 3072];
// flash pre-split buffers: per-head rows of 192
__device__ __align__(16) __nv_bfloat16 g_q3f[HH * TT * 192];   // [h][t][hi,lo,hi] (scaled)
__device__ __align__(16) __nv_bfloat16 g_k3f[HH * TT * 192];   // [h][t][hi,hi,lo]
__device__ __align__(16) __nv_bfloat16 g_v3f[HH * DD * 6144];  // [h][d][kt*192 + hi,hi,lo over keys]

struct Src6 { const float* s[6]; };
struct Out5 { float* p[5]; };

// ============================ PTX helpers ============================
__device__ __forceinline__ uint32_t smem_u32(const void* p) {
    uint32_t a;
    asm("{ .reg .u64 t; cvta.to.shared.u64 t, %1; cvt.u32.u64 %0, t; }" : "=r"(a) : "l"(p));
    return a;
}
__device__ __forceinline__ void cp_async16(uint32_t s, const void* g) {
    asm volatile("cp.async.cg.shared.global [%0], [%1], 16;" :: "r"(s), "l"(g));
}
__device__ __forceinline__ void cp_commit() { asm volatile("cp.async.commit_group;"); }
template<int N> __device__ __forceinline__ void cp_wait() {
    asm volatile("cp.async.wait_group %0;" :: "n"(N) : "memory");
}
__device__ __forceinline__ void ldmx4(uint32_t& r0, uint32_t& r1, uint32_t& r2, uint32_t& r3,
                                      uint32_t addr) {
    asm volatile("ldmatrix.sync.aligned.m8n8.x4.shared.b16 {%0,%1,%2,%3}, [%4];"
                 : "=r"(r0), "=r"(r1), "=r"(r2), "=r"(r3) : "r"(addr));
}
__device__ __forceinline__ void mma_bf16(float* d, const uint32_t* a, const uint32_t* b) {
    asm volatile("mma.sync.aligned.m16n8k16.row.col.f32.bf16.bf16.f32 "
                 "{%0,%1,%2,%3}, {%4,%5,%6,%7}, {%8,%9}, {%0,%1,%2,%3};"
                 : "+f"(d[0]), "+f"(d[1]), "+f"(d[2]), "+f"(d[3])
                 : "r"(a[0]), "r"(a[1]), "r"(a[2]), "r"(a[3]), "r"(b[0]), "r"(b[1]));
}
__device__ __forceinline__ uint32_t pack2(__nv_bfloat16 a, __nv_bfloat16 b) {
    __nv_bfloat162 t(a, b);
    return *reinterpret_cast<uint32_t*>(&t);
}

// BK=64, 2-stage: rows padded to 72 elements (144B)
#define HROW 144
#define HOPER (128 * HROW)
#define HSTAGE (2 * HOPER)
#define HMMA_SMEM (2 * HSTAGE)

// =====================================================================
// HMMA mainloop (BK=64, 2-stage), warp layout 2M x 4N (64x32 per warp)
// =====================================================================
__device__ __forceinline__ void hmma_body(const __nv_bfloat16* __restrict__ A,
                                          const __nv_bfloat16* __restrict__ B,
                                          float acc[4][4][4],
                                          int m0, int n0, int K3,
                                          int kbeg, int klen,
                                          __nv_bfloat16* sm) {
    const int tid = threadIdx.x;
    const int nchunk = klen >> 6;
    const int warp = tid >> 5, lane = tid & 31;
    const int wm = warp & 1, wn = warp >> 1;
    const uint32_t smb = smem_u32(sm);

    auto load_stage = [&](int cc, int s) {
        const uint32_t ab = smb + s * HSTAGE;
        const uint32_t bb = ab + HOPER;
        const int k0 = kbeg + cc * 64;
#pragma unroll
        for (int i = 0; i < 4; i++) {
            int idx = tid + i * 256;
            int row = idx >> 3, cg = idx & 7;
            cp_async16(ab + row * HROW + cg * 16, A + (size_t)(m0 + row) * K3 + k0 + cg * 8);
            cp_async16(bb + row * HROW + cg * 16, B + (size_t)(n0 + row) * K3 + k0 + cg * 8);
        }
        cp_commit();
    };

    load_stage(0, 0);
    load_stage(1, 1);

    const int lrow = lane & 15;
    const int lcol = (lane >> 4) << 3;

    for (int c = 0; c < nchunk; c++) {
        cp_wait<1>();
        __syncthreads();
        const uint32_t ab = smb + (c & 1) * HSTAGE;
        const uint32_t bb = ab + HOPER;
#pragma unroll
        for (int ks = 0; ks < 4; ks++) {
            const uint32_t coff = (ks * 16 + lcol) * 2;
            uint32_t a[4][4], b[4][2];
#pragma unroll
            for (int mt = 0; mt < 4; mt++)
                ldmx4(a[mt][0], a[mt][1], a[mt][2], a[mt][3],
                      ab + (uint32_t)(wm * 64 + mt * 16 + lrow) * HROW + coff);
#pragma unroll
            for (int bp = 0; bp < 2; bp++) {
                uint32_t r0, r1, r2, r3;
                ldmx4(r0, r1, r2, r3,
                      bb + (uint32_t)(wn * 32 + bp * 16 + lrow) * HROW + coff);
                b[bp * 2][0] = r0; b[bp * 2][1] = r2;
                b[bp * 2 + 1][0] = r1; b[bp * 2 + 1][1] = r3;
            }
#pragma unroll
            for (int mt = 0; mt < 4; mt++)
#pragma unroll
                for (int nt = 0; nt < 4; nt++) mma_bf16(acc[mt][nt], a[mt], b[nt]);
        }
        __syncthreads();
        if (c + 2 < nchunk) load_stage(c + 2, c & 1);
    }
}

__device__ __forceinline__ void hmma_epi(float acc[4][4][4], float* C, int m0, int ncol0) {
    const int lane = threadIdx.x & 31, warp = threadIdx.x >> 5;
    const int wm = warp & 1, wn = warp >> 1;
    const int erow = lane >> 2, ecol = (lane & 3) * 2;
#pragma unroll
    for (int mt = 0; mt < 4; mt++) {
        const int r0 = m0 + wm * 64 + mt * 16 + erow;
#pragma unroll
        for (int nt = 0; nt < 4; nt++) {
            const int cc = ncol0 + wn * 32 + nt * 8 + ecol;
            *(float2*)&C[(size_t)r0 * 1024 + cc] = make_float2(acc[mt][nt][0], acc[mt][nt][1]);
            *(float2*)&C[(size_t)(r0 + 8) * 1024 + cc] = make_float2(acc[mt][nt][2], acc[mt][nt][3]);
        }
    }
}

template<bool CAUSAL>
__global__ void __launch_bounds__(256, 2) hmma_gemmz(const __nv_bfloat16* __restrict__ A,
                                                     const __nv_bfloat16* __restrict__ B,
                                                     float* __restrict__ C0,
                                                     float* __restrict__ C1, int K3) {
    extern __shared__ __nv_bfloat16 sm[];
    float acc[4][4][4];
#pragma unroll
    for (int i = 0; i < 4; i++)
#pragma unroll
        for (int j = 0; j < 4; j++)
#pragma unroll
            for (int t = 0; t < 4; t++) acc[i][j][t] = 0.f;
    const int m0 = blockIdx.y * 128, n0 = blockIdx.x * 128;
    const int kc = CAUSAL ? ((m0 + 128) * 3 < K3 ? (m0 + 128) * 3 : K3) : K3;
    const int half = kc >> 1;
    hmma_body(A, B, acc, m0, n0, K3, blockIdx.z * half, half, sm);
    hmma_epi(acc, blockIdx.z ? C1 : C0, m0, n0);
}

__global__ void __launch_bounds__(256, 2) hmma_gemm5(const __nv_bfloat16* __restrict__ A,
                                                     const __nv_bfloat16* __restrict__ B,
                                                     Out5 outs, int K3) {
    extern __shared__ __nv_bfloat16 sm[];
    float acc[4][4][4];
#pragma unroll
    for (int i = 0; i < 4; i++)
#pragma unroll
        for (int j = 0; j < 4; j++)
#pragma unroll
            for (int t = 0; t < 4; t++) acc[i][j][t] = 0.f;
    const int m0 = blockIdx.y * 128, n0 = blockIdx.x * 128;
    hmma_body(A, B, acc, m0, n0, K3, 0, K3, sm);
    hmma_epi(acc, outs.p[blockIdx.x >> 3], m0, (blockIdx.x & 7) * 128);
}

// =====================================================================
// flash pre-split conversions
// =====================================================================
__global__ void convQK3(const float* __restrict__ q, const float* __restrict__ k,
                        __nv_bfloat16* __restrict__ q3, __nv_bfloat16* __restrict__ k3) {
    const int idx = blockIdx.x * 256 + threadIdx.x;   // t*1024 + h*64 + d
    const int t = idx >> 10, hd = idx & 1023;
    const int h = hd >> 6, d = hd & 63;
    const size_t orow = ((size_t)h * TT + t) * 192;
    const float QSCALE = 0.125f * LOG2E;
    float qv = q[idx] * QSCALE;
    __nv_bfloat16 qhi = __float2bfloat16(qv);
    __nv_bfloat16 qlo = __float2bfloat16(qv - __bfloat162float(qhi));
    q3[orow + d] = qhi; q3[orow + 64 + d] = qlo; q3[orow + 128 + d] = qhi;
    float kv = k[idx];
    __nv_bfloat16 khi = __float2bfloat16(kv);
    __nv_bfloat16 klo = __float2bfloat16(kv - __bfloat162float(khi));
    k3[orow + d] = khi; k3[orow + 64 + d] = khi; k3[orow + 128 + d] = klo;
}

// v3f[h][d][kt*192 + {hi,hi,lo} over 64 keys]
__global__ void convV3T(const float* __restrict__ v, __nv_bfloat16* __restrict__ v3) {
    __shared__ float t[64][65];
    const int kt = blockIdx.x, h = blockIdx.y;
    const int tid = threadIdx.x;
    // load 64 keys x 64 d
    for (int i = tid; i < 4096; i += 256) {
        int key = i >> 6, d = i & 63;
        t[d][key] = v[(size_t)(kt * 64 + key) * HD + h * 64 + d];
    }
    __syncthreads();
    for (int i = tid; i < 4096; i += 256) {
        int d = i >> 6, j = i & 63;
        float x = t[d][j];
        __nv_bfloat16 hi = __float2bfloat16(x);
        __nv_bfloat16 lo = __float2bfloat16(x - __bfloat162float(hi));
        __nv_bfloat16* base = v3 + ((size_t)h * 64 + d) * 6144 + kt * 192;
        base[j] = hi; base[64 + j] = hi; base[128 + j] = lo;
    }
}

// =====================================================================
// branch 1: flash attention, Q tile 128 rows, cp.async pre-split loads
// =====================================================================
#define FL3_SMEM ((128 + 64 + 64) * 400)   // 102400 B

__global__ void __launch_bounds__(256) flash_hmma3(const __nv_bfloat16* __restrict__ q3,
                                                   const __nv_bfloat16* __restrict__ k3,
                                                   const __nv_bfloat16* __restrict__ v3,
                                                   float* __restrict__ out) {
    extern __shared__ __nv_bfloat16 fsm[];
    const int h = blockIdx.y, m0 = blockIdx.x * 128;
    const int tid = threadIdx.x, warp = tid >> 5, lane = tid & 31;
    const uint32_t smb = smem_u32(fsm);
    const uint32_t Qb = smb;
    const uint32_t Kb = smb + 128 * 400;
    const uint32_t Vb = Kb + 64 * 400;
    const int lrow = lane & 15, lcol = (lane >> 4) << 3;

    // Q: 128 rows x 24 chunks via cp.async
    const __nv_bfloat16* qbase = q3 + ((size_t)h * TT + m0) * 192;
#pragma unroll
    for (int i = 0; i < 12; i++) {
        int c = tid + i * 256;
        int row = c / 24, cg = c % 24;
        cp_async16(Qb + row * 400 + cg * 16, qbase + (size_t)row * 192 + cg * 8);
    }
    cp_commit();

    float m_lo = -1e30f, m_hi = -1e30f, l_lo = 0.f, l_hi = 0.f;
    float O[8][4];
#pragma unroll
    for (int nt = 0; nt < 8; nt++)
#pragma unroll
        for (int t = 0; t < 4; t++) O[nt][t] = 0.f;

    for (int n0 = 0; n0 <= m0 + 64; n0 += 64) {
        __syncthreads();
        // K and V tiles via cp.async
        const __nv_bfloat16* kbase = k3 + ((size_t)h * TT + n0) * 192;
        const __nv_bfloat16* vbase = v3 + (size_t)h * 64 * 6144 + (n0 >> 6) * 192;
#pragma unroll
        for (int i = 0; i < 6; i++) {
            int c = tid + i * 256;
            int row = c / 24, cg = c % 24;
            cp_async16(Kb + row * 400 + cg * 16, kbase + (size_t)row * 192 + cg * 8);
            cp_async16(Vb + row * 400 + cg * 16, vbase + (size_t)row * 6144 + cg * 8);
        }
        cp_commit();
        cp_wait<0>();
        __syncthreads();

        float s[8][4];
#pragma unroll
        for (int nt = 0; nt < 8; nt++)
#pragma unroll
            for (int t = 0; t < 4; t++) s[nt][t] = 0.f;
#pragma unroll
        for (int ks = 0; ks < 12; ks++) {
            const uint32_t coff = (ks * 16 + lcol) * 2;
            uint32_t a[4], b[8][2];
            ldmx4(a[0], a[1], a[2], a[3], Qb + (uint32_t)(warp * 16 + lrow) * 400 + coff);
#pragma unroll
            for (int bp = 0; bp < 4; bp++) {
                uint32_t r0, r1, r2, r3;
                ldmx4(r0, r1, r2, r3, Kb + (uint32_t)(bp * 16 + lrow) * 400 + coff);
                b[bp * 2][0] = r0; b[bp * 2][1] = r2;
                b[bp * 2 + 1][0] = r1; b[bp * 2 + 1][1] = r3;
            }
#pragma unroll
            for (int nt = 0; nt < 8; nt++) mma_bf16(s[nt], a, b[nt]);
        }

        if (n0 >= m0) {
            const int rl = m0 + warp * 16 + (lane >> 2);
            const int cb = n0 + (lane & 3) * 2;
#pragma unroll
            for (int nt = 0; nt < 8; nt++) {
                int c0 = cb + nt * 8, c1 = c0 + 1;
                if (c0 > rl) s[nt][0] = -1e30f;
                if (c1 > rl) s[nt][1] = -1e30f;
                if (c0 > rl + 8) s[nt][2] = -1e30f;
                if (c1 > rl + 8) s[nt][3] = -1e30f;
            }
        }

        float rmx_lo = -1e30f, rmx_hi = -1e30f;
#pragma unroll
        for (int nt = 0; nt < 8; nt++) {
            rmx_lo = fmaxf(rmx_lo, fmaxf(s[nt][0], s[nt][1]));
            rmx_hi = fmaxf(rmx_hi, fmaxf(s[nt][2], s[nt][3]));
        }
#pragma unroll
        for (int o = 1; o < 4; o <<= 1) {
            rmx_lo = fmaxf(rmx_lo, __shfl_xor_sync(0xffffffffu, rmx_lo, o));
            rmx_hi = fmaxf(rmx_hi, __shfl_xor_sync(0xffffffffu, rmx_hi, o));
        }
        float mn_lo = fmaxf(m_lo, rmx_lo), mn_hi = fmaxf(m_hi, rmx_hi);
        float corr_lo = exp2f(m_lo - mn_lo), corr_hi = exp2f(m_hi - mn_hi);
        m_lo = mn_lo; m_hi = mn_hi;
        float rs_lo = 0.f, rs_hi = 0.f;
#pragma unroll
        for (int nt = 0; nt < 8; nt++) {
            s[nt][0] = exp2f(s[nt][0] - mn_lo); rs_lo += s[nt][0];
            s[nt][1] = exp2f(s[nt][1] - mn_lo); rs_lo += s[nt][1];
            s[nt][2] = exp2f(s[nt][2] - mn_hi); rs_hi += s[nt][2];
            s[nt][3] = exp2f(s[nt][3] - mn_hi); rs_hi += s[nt][3];
        }
#pragma unroll
        for (int o = 1; o < 4; o <<= 1) {
            rs_lo += __shfl_xor_sync(0xffffffffu, rs_lo, o);
            rs_hi += __shfl_xor_sync(0xffffffffu, rs_hi, o);
        }
        l_lo = l_lo * corr_lo + rs_lo;
        l_hi = l_hi * corr_hi + rs_hi;
#pragma unroll
        for (int nt = 0; nt < 8; nt++) {
            O[nt][0] *= corr_lo; O[nt][1] *= corr_lo;
            O[nt][2] *= corr_hi; O[nt][3] *= corr_hi;
        }

        uint32_t phi[4][4], plo[4][4];
#pragma unroll
        for (int kk = 0; kk < 4; kk++) {
            const int n0t = 2 * kk, n1t = 2 * kk + 1;
            __nv_bfloat16 h00 = __float2bfloat16(s[n0t][0]);
            __nv_bfloat16 h01 = __float2bfloat16(s[n0t][1]);
            __nv_bfloat16 h02 = __float2bfloat16(s[n0t][2]);
            __nv_bfloat16 h03 = __float2bfloat16(s[n0t][3]);
            __nv_bfloat16 h10 = __float2bfloat16(s[n1t][0]);
            __nv_bfloat16 h11 = __float2bfloat16(s[n1t][1]);
            __nv_bfloat16 h12 = __float2bfloat16(s[n1t][2]);
            __nv_bfloat16 h13 = __float2bfloat16(s[n1t][3]);
            phi[kk][0] = pack2(h00, h01);
            phi[kk][1] = pack2(h02, h03);
            phi[kk][2] = pack2(h10, h11);
            phi[kk][3] = pack2(h12, h13);
            plo[kk][0] = pack2(__float2bfloat16(s[n0t][0] - __bfloat162float(h00)),
                               __float2bfloat16(s[n0t][1] - __bfloat162float(h01)));
            plo[kk][1] = pack2(__float2bfloat16(s[n0t][2] - __bfloat162float(h02)),
                               __float2bfloat16(s[n0t][3] - __bfloat162float(h03)));
            plo[kk][2] = pack2(__float2bfloat16(s[n1t][0] - __bfloat162float(h10)),
                               __float2bfloat16(s[n1t][1] - __bfloat162float(h11)));
            plo[kk][3] = pack2(__float2bfloat16(s[n1t][2] - __bfloat162float(h12)),
                               __float2bfloat16(s[n1t][3] - __bfloat162float(h13)));
        }

#pragma unroll
        for (int ks = 0; ks < 12; ks++) {
            const uint32_t* a = (ks < 4) ? phi[ks] : (ks < 8) ? plo[ks - 4] : phi[ks - 8];
            const uint32_t coff = (ks * 16 + lcol) * 2;
            uint32_t b[8][2];
#pragma unroll
            for (int bp = 0; bp < 4; bp++) {
                uint32_t r0, r1, r2, r3;
                ldmx4(r0, r1, r2, r3, Vb + (uint32_t)(bp * 16 + lrow) * 400 + coff);
                b[bp * 2][0] = r0; b[bp * 2][1] = r2;
                b[bp * 2 + 1][0] = r1; b[bp * 2 + 1][1] = r3;
            }
#pragma unroll
            for (int nt = 0; nt < 8; nt++) mma_bf16(O[nt], a, b[nt]);
        }
    }

    const float inv_lo = 1.f / l_lo, inv_hi = 1.f / l_hi;
    const int rl = m0 + warp * 16 + (lane >> 2);
#pragma unroll
    for (int nt = 0; nt < 8; nt++) {
        const int col = h * 64 + nt * 8 + (lane & 3) * 2;
        *(float2*)&out[(size_t)rl * HD + col] = make_float2(O[nt][0] * inv_lo, O[nt][1] * inv_lo);
        *(float2*)&out[(size_t)(rl + 8) * HD + col] = make_float2(O[nt][2] * inv_hi, O[nt][3] * inv_hi);
    }
}

// =====================================================================
// conversions (weights, x, echo)
// =====================================================================
__global__ void conv3w6(Src6 src, __nv_bfloat16* __restrict__ D) {
    const int w = blockIdx.y;
    const int idx = blockIdx.x * 256 + threadIdx.x;
    const int m = idx >> 10, k = idx & 1023;
    float x = src.s[w][idx];
    __nv_bfloat16 hi = __float2bfloat16(x);
    __nv_bfloat16 lo = __float2bfloat16(x - __bfloat162float(hi));
    __nv_bfloat16* row = D + (size_t)(w * 1024 + m) * 3072;
    row[k] = hi;
    row[1024 + k] = hi;
    row[2048 + k] = lo;
}

template<bool APAT>
__global__ void conv3(const float* __restrict__ S, __nv_bfloat16* __restrict__ D, int K) {
    const int idx = blockIdx.x * 256 + threadIdx.x;
    const int m = idx / K, k = idx - m * K;
    float x = S[idx];
    __nv_bfloat16 hi = __float2bfloat16(x);
    __nv_bfloat16 lo = __float2bfloat16(x - __bfloat162float(hi));
    const size_t ro = (size_t)m * 3 * K;
    D[ro + k] = hi;
    D[ro + K + k] = APAT ? lo : hi;
    D[ro + 2 * K + k] = APAT ? hi : lo;
}

__global__ void conv3Tg(const float* __restrict__ S, __nv_bfloat16* __restrict__ D,
                        int K, int N) {
    __shared__ float t[32][33];
    const int k0 = blockIdx.x * 32, n0 = blockIdx.y * 32;
    const int tx = threadIdx.x & 31, ty = threadIdx.x >> 5;
    for (int i = ty; i < 32; i += 8) t[i][tx] = S[(size_t)(k0 + i) * N + n0 + tx];
    __syncthreads();
    const int K3 = 3 * K;
    for (int i = ty; i < 32; i += 8) {
        const int n = n0 + i, k = k0 + tx;
        const int g = k >> 6, j = k & 63;
        float x = t[tx][i];
        __nv_bfloat16 hi = __float2bfloat16(x);
        __nv_bfloat16 lo = __float2bfloat16(x - __bfloat162float(hi));
        __nv_bfloat16* base = D + (size_t)n * K3 + g * 192;
        base[j] = hi;
        base[64 + j] = hi;
        base[128 + j] = lo;
    }
}

// ---------------- branch 2: two-pass blocked scan ---------------------
__global__ void __launch_bounds__(256) krrp(const float* __restrict__ r,
                                            const float* __restrict__ rv,
                                            float* __restrict__ out) {
    __shared__ float w[2048];
    __shared__ float rl[2048];
    __shared__ float red[256];
    __shared__ float Sg[4][64];
    const int h = blockIdx.x, tid = threadIdx.x;
    const float Cc = 0.125f * LOG2E;
    float vloc[8], lm = -1e30f;
#pragma unroll
    for (int i = 0; i < 8; i++) {
        float vv = r[h * 2048 + tid * 8 + i] * Cc;
        vloc[i] = vv;
        lm = fmaxf(lm, vv);
    }
    red[tid] = lm; __syncthreads();
    for (int s = 128; s; s >>= 1) { if (tid < s) red[tid] = fmaxf(red[tid], red[tid + s]); __syncthreads(); }
    float M = red[0];
    __syncthreads();
    float run = 0.f, pre[8];
#pragma unroll
    for (int i = 0; i < 8; i++) {
        float e = exp2f(vloc[i] - M);
        w[tid * 8 + i] = e;
        run += e;
        pre[i] = run;
    }
    red[tid] = run; __syncthreads();
    for (int s = 1; s < 256; s <<= 1) {
        float t = (tid >= s) ? red[tid - s] : 0.f;
        __syncthreads();
        red[tid] += t;
        __syncthreads();
    }
    float excl = red[tid] - run;
#pragma unroll
    for (int i = 0; i < 8; i++) rl[tid * 8 + i] = 1.f / (excl + pre[i]);
    __syncthreads();

    const int g = tid >> 6, d = tid & 63;
    const int t0 = g * 512, t1 = t0 + 512;
    const float* rp = rv + h * 64 + d;
    float s1 = 0.f;
#pragma unroll 4
    for (int t = t0; t < t1; t++) s1 += w[t] * rp[(size_t)t * 1024];
    Sg[g][d] = s1;
    __syncthreads();
    float base = 0.f;
#pragma unroll
    for (int gg = 0; gg < 3; gg++)
        if (gg < g) base += Sg[gg][d];
    float acc = base;
    float* op = out + h * 64 + d;
#pragma unroll 4
    for (int t = t0; t < t1; t++) {
        acc += w[t] * rp[(size_t)t * 1024];
        op[(size_t)t * 1024] = acc * rl[t];
    }
}

// ---------------- branch 3 probabilities -> grouped split bf16 -------
__global__ void __launch_bounds__(256) kjp3(const float* __restrict__ sc,
                                            __nv_bfloat16* __restrict__ P3) {
    __shared__ float sk[2048];
    __shared__ float se[2048];
    __shared__ float red[256];
    const int qq = blockIdx.x, tid = threadIdx.x;
    for (int t = tid; t < 2048; t += 256) sk[t] = sc[t];
    __syncthreads();
    const float sq = sk[qq] * LOG2E;
    float lm = -1e30f;
    for (int t = tid; t <= qq; t += 256) lm = fmaxf(lm, sq * sk[t]);
    red[tid] = lm; __syncthreads();
    for (int s = 128; s; s >>= 1) { if (tid < s) red[tid] = fmaxf(red[tid], red[tid + s]); __syncthreads(); }
    float M = red[0];
    __syncthreads();
    float ls = 0.f;
    for (int t = tid; t <= qq; t += 256) {
        float e = exp2f(sq * sk[t] - M);
        se[t] = e;
        ls += e;
    }
    red[tid] = ls; __syncthreads();
    for (int s = 128; s; s >>= 1) { if (tid < s) red[tid] += red[tid + s]; __syncthreads(); }
    const float rinv = 1.f / red[0];
    __nv_bfloat16* Prow = P3 + (size_t)qq * 6144;
    for (int t = tid; t < 2048; t += 256) {
        float p = (t <= qq) ? se[t] * rinv : 0.f;
        __nv_bfloat16 hi = __float2bfloat16(p);
        __nv_bfloat16 lo = __float2bfloat16(p - __bfloat162float(hi));
        const int g = t >> 6, j = t & 63;
        __nv_bfloat16* base = Prow + g * 192;
        base[j] = hi;
        base[64 + j] = lo;
        base[128 + j] = hi;
    }
}

// ---------------- r[h,t] ----------------------------------------------
__global__ void kr(const float* __restrict__ x, const float* __restrict__ wr,
                   float* __restrict__ r) {
    const int h = blockIdx.y;
    const int t = blockIdx.x * 128 + threadIdx.x;
    const float* wp = wr + (size_t)h * EE * TT + t;
    const float* xp = x + (size_t)t * EE;
    float acc = 0.f;
#pragma unroll 8
    for (int e = 0; e < EE; e++) acc += xp[e] * wp[(size_t)e * TT];
    r[h * TT + t] = acc;
}

// ---------------- scores[t] = ||echo[t]||^2 / 32 ----------------------
__global__ void kscores2(const float* __restrict__ echo, float* __restrict__ sc) {
    const int t = blockIdx.x * 8 + (threadIdx.x >> 5);
    const int lane = threadIdx.x & 31;
    const float* ep = echo + (size_t)t * EE;
    float a = 0.f;
#pragma unroll 4
    for (int e = lane * 4; e < EE; e += 128) {
        float4 v = *(const float4*)(ep + e);
        a += v.x * v.x + v.y * v.y + v.z * v.z + v.w * v.w;
    }
#pragma unroll
    for (int o = 16; o > 0; o >>= 1) a += __shfl_xor_sync(0xffffffffu, a, o);
    if (lane == 0) sc[t] = a * (1.f / 32.f);
}

// ---------------- gated combine (o3 = a + b) -> split bf16 ------------
__global__ void kcombine3(const float* __restrict__ o1, const float* __restrict__ o2,
                          const float* __restrict__ o3a, const float* __restrict__ o3b,
                          const float* __restrict__ gate,
                          __nv_bfloat16* __restrict__ comb3) {
    const int idx = blockIdx.x * 256 + threadIdx.x;
    const int c = idx & (HD - 1);
    const int h = c >> 6;
    float g0 = gate[h * 3 + 0], g1 = gate[h * 3 + 1], g2 = gate[h * 3 + 2];
    float mx = fmaxf(g0, fmaxf(g1, g2));
    float e0 = __expf(g0 - mx), e1 = __expf(g1 - mx), e2 = __expf(g2 - mx);
    float inv = 1.f / (e0 + e1 + e2);
    float val = (e0 * o1[idx] + e1 * o2[idx] + e2 * (o3a[idx] + o3b[idx])) * inv;
    __nv_bfloat16 hi = __float2bfloat16(val);
    __nv_bfloat16 lo = __float2bfloat16(val - __bfloat162float(hi));
    const int m = idx >> 10, k = idx & 1023;
    __nv_bfloat16* row = comb3 + (size_t)m * 3072;
    row[k] = hi;
    row[1024 + k] = lo;
    row[2048 + k] = hi;
}

// ---------------- final add ------------------------------------------
__global__ void kadd(const float* __restrict__ a, const float* __restrict__ b,
                     float* __restrict__ out) {
    const int idx = blockIdx.x * 256 + threadIdx.x;
    out[idx] = a[idx] + b[idx];
}

// ---------------- launch: multi-stream fork/join graph -----------------
extern "C" void kernel_launch(void* const* d_in, const int* in_sizes, int n_in,
                              void* d_out, int out_size) {
    const float* x    = (const float*)d_in[0];
    const float* wq   = (const float*)d_in[1];
    const float* wk   = (const float*)d_in[2];
    const float* wv   = (const float*)d_in[3];
    const float* wr   = (const float*)d_in[4];
    const float* wvr  = (const float*)d_in[5];
    const float* wj   = (const float*)d_in[6];
    const float* gate = (const float*)d_in[7];
    const float* wo   = (const float*)d_in[8];
    float* out = (float*)d_out;

    float *q, *k, *v, *rv, *echo, *r, *sc, *o1, *o2, *o3a, *o3b, *f0, *f1;
    __nv_bfloat16 *x3, *w6, *echoT3, *P3, *comb3, *q3f, *k3f, *v3f;
    cudaGetSymbolAddress((void**)&q, g_q);
    cudaGetSymbolAddress((void**)&k, g_k);
    cudaGetSymbolAddress((void**)&v, g_v);
    cudaGetSymbolAddress((void**)&rv, g_rv);
    cudaGetSymbolAddress((void**)&echo, g_echo);
    cudaGetSymbolAddress((void**)&r, g_r);
    cudaGetSymbolAddress((void**)&sc, g_sc);
    cudaGetSymbolAddress((void**)&o1, g_o1);
    cudaGetSymbolAddress((void**)&o2, g_o2);
    cudaGetSymbolAddress((void**)&o3a, g_o3a);
    cudaGetSymbolAddress((void**)&o3b, g_o3b);
    cudaGetSymbolAddress((void**)&f0, g_f0);
    cudaGetSymbolAddress((void**)&f1, g_f1);
    cudaGetSymbolAddress((void**)&x3, g_x3);
    cudaGetSymbolAddress((void**)&w6, g_w6);
    cudaGetSymbolAddress((void**)&echoT3, g_echoT3);
    cudaGetSymbolAddress((void**)&P3, g_P3);
    cudaGetSymbolAddress((void**)&comb3, g_comb3);
    cudaGetSymbolAddress((void**)&q3f, g_q3f);
    cudaGetSymbolAddress((void**)&k3f, g_k3f);
    cudaGetSymbolAddress((void**)&v3f, g_v3f);

    static cudaStream_t sB = nullptr, sC = nullptr;
    static cudaEvent_t evFork, evProj, evO1, evO2, evT;
    if (!sB) {
        cudaStreamCreateWithFlags(&sB, cudaStreamNonBlocking);
        cudaStreamCreateWithFlags(&sC, cudaStreamNonBlocking);
        cudaEventCreateWithFlags(&evFork, cudaEventDisableTiming);
        cudaEventCreateWithFlags(&evProj, cudaEventDisableTiming);
        cudaEventCreateWithFlags(&evO1, cudaEventDisableTiming);
        cudaEventCreateWithFlags(&evO2, cudaEventDisableTiming);
        cudaEventCreateWithFlags(&evT, cudaEventDisableTiming);
        cudaFuncSetAttribute(hmma_gemmz<false>, cudaFuncAttributeMaxDynamicSharedMemorySize, HMMA_SMEM);
        cudaFuncSetAttribute(hmma_gemmz<true>, cudaFuncAttributeMaxDynamicSharedMemorySize, HMMA_SMEM);
        cudaFuncSetAttribute(hmma_gemm5, cudaFuncAttributeMaxDynamicSharedMemorySize, HMMA_SMEM);
        cudaFuncSetAttribute(flash_hmma3, cudaFuncAttributeMaxDynamicSharedMemorySize, FL3_SMEM);
    }

    const int X = 2048 * 1024 / 256;

    // fork: stream C starts kr immediately
    cudaEventRecord(evFork, 0);
    cudaStreamWaitEvent(sC, evFork, 0);
    kr<<<dim3(16, 16), 128, 0, sC>>>(x, wr, r);

    // main: conversions + batched projection
    Src6 src{{wq, wk, wv, wvr, wj, wo}};
    conv3w6<<<dim3(4096, 6), 256>>>(src, w6);
    conv3<true><<<X, 256>>>(x, x3, 1024);
    Out5 outs{{q, k, v, rv, echo}};
    hmma_gemm5<<<dim3(40, 16), 256, HMMA_SMEM>>>(x3, w6, outs, 3072);
    cudaEventRecord(evProj, 0);

    // stream B: echo transpose (for main's o3 gemm), flash pre-split, flash
    cudaStreamWaitEvent(sB, evProj, 0);
    conv3Tg<<<dim3(64, 32), 256, 0, sB>>>(echo, echoT3, 2048, 1024);
    cudaEventRecord(evT, sB);
    convQK3<<<X, 256, 0, sB>>>(q, k, q3f, k3f);
    convV3T<<<dim3(32, 16), 256, 0, sB>>>(v, v3f);
    flash_hmma3<<<dim3(16, 16), 256, FL3_SMEM, sB>>>(q3f, k3f, v3f, o1);
    cudaEventRecord(evO1, sB);

    // stream C: krrp
    cudaStreamWaitEvent(sC, evProj, 0);
    krrp<<<16, 256, 0, sC>>>(r, rv, o2);
    cudaEventRecord(evO2, sC);

    // main: janus chain + split-K causal GEMM
    kscores2<<<TT / 8, 256>>>(echo, sc);
    kjp3<<<TT, 256>>>(sc, P3);
    cudaStreamWaitEvent(0, evT, 0);
    hmma_gemmz<true><<<dim3(8, 16, 2), 256, HMMA_SMEM>>>(P3, echoT3, o3a, o3b, 6144);

    // join + combine + split-K output projection
    cudaStreamWaitEvent(0, evO1, 0);
    cudaStreamWaitEvent(0, evO2, 0);
    kcombine3<<<(TT * HD) / 256, 256>>>(o1, o2, o3a, o3b, gate, comb3);
    hmma_gemmz<false><<<dim3(8, 16, 2), 256, HMMA_SMEM>>>(comb3, w6 + (size_t)5 * 1024 * 3072,
                                                          f0, f1, 3072);
    kadd<<<(TT * HD) / 256, 256>>>(f0, f1, out);
}

// round 13
// speedup vs baseline: 1.0212x; 1.0212x over previous
#include <cuda_runtime.h>
#include <cuda_bf16.h>
#include <cstdint>

#define TT 2048
#define EE 1024
#define HH 16
#define DD 64
#define HD 1024
#define LOG2E 1.4426950408889634f

// ---------------- fp32 scratch ----------------
__device__ __align__(16) float g_q[TT * HD];
__device__ __align__(16) float g_k[TT * HD];
__device__ __align__(16) float g_v[TT * HD];
__device__ __align__(16) float g_rv[TT * HD];
__device__ __align__(16) float g_echo[TT * EE];
__device__ __align__(16) float g_r[HH * TT];
__device__ __align__(16) float g_sc[TT];
__device__ __align__(16) float g_o1[TT * HD];
__device__ __align__(16) float g_o2[TT * HD];
__device__ __align__(16) float g_o3a[TT * EE];
__device__ __align__(16) float g_o3b[TT * EE];
__device__ __align__(16) float g_f0[TT * EE];
__device__ __align__(16) float g_f1[TT * EE];

// ---------------- bf16 triple-split scratch ----------------
__device__ __align__(16) __nv_bfloat16 g_x3[TT * 3072];
__device__ __align__(16) __nv_bfloat16 g_w6[6144 * 3072];
__device__ __align__(16) __nv_bfloat16 g_echoT3[1024 * 6144];
__device__ __align__(16) __nv_bfloat16 g_P3[TT * 6144];
__device__ __align__(16) __nv_bfloat16 g_comb3[TT * 3072];
// flash pre-split buffers
__device__ __align__(16) __nv_bfloat16 g_q3f[HH * TT * 192];
__device__ __align__(16) __nv_bfloat16 g_k3f[HH * TT * 192];
__device__ __align__(16) __nv_bfloat16 g_v3f[HH * DD * 6144];

struct Src6 { const float* s[6]; };
struct Out5 { float* p[5]; };

// ============================ PTX helpers ============================
__device__ __forceinline__ uint32_t smem_u32(const void* p) {
    uint32_t a;
    asm("{ .reg .u64 t; cvta.to.shared.u64 t, %1; cvt.u32.u64 %0, t; }" : "=r"(a) : "l"(p));
    return a;
}
__device__ __forceinline__ void cp_async16(uint32_t s, const void* g) {
    asm volatile("cp.async.cg.shared.global [%0], [%1], 16;" :: "r"(s), "l"(g));
}
__device__ __forceinline__ void cp_commit() { asm volatile("cp.async.commit_group;"); }
template<int N> __device__ __forceinline__ void cp_wait() {
    asm volatile("cp.async.wait_group %0;" :: "n"(N) : "memory");
}
__device__ __forceinline__ void ldmx4(uint32_t& r0, uint32_t& r1, uint32_t& r2, uint32_t& r3,
                                      uint32_t addr) {
    asm volatile("ldmatrix.sync.aligned.m8n8.x4.shared.b16 {%0,%1,%2,%3}, [%4];"
                 : "=r"(r0), "=r"(r1), "=r"(r2), "=r"(r3) : "r"(addr));
}
__device__ __forceinline__ void mma_bf16(float* d, const uint32_t* a, const uint32_t* b) {
    asm volatile("mma.sync.aligned.m16n8k16.row.col.f32.bf16.bf16.f32 "
                 "{%0,%1,%2,%3}, {%4,%5,%6,%7}, {%8,%9}, {%0,%1,%2,%3};"
                 : "+f"(d[0]), "+f"(d[1]), "+f"(d[2]), "+f"(d[3])
                 : "r"(a[0]), "r"(a[1]), "r"(a[2]), "r"(a[3]), "r"(b[0]), "r"(b[1]));
}
__device__ __forceinline__ uint32_t pack2(__nv_bfloat16 a, __nv_bfloat16 b) {
    __nv_bfloat162 t(a, b);
    return *reinterpret_cast<uint32_t*>(&t);
}

// BK=64, 2-stage: rows padded to 72 elements (144B)
#define HROW 144
#define HOPER (128 * HROW)
#define HSTAGE (2 * HOPER)
#define HMMA_SMEM (2 * HSTAGE)

// =====================================================================
// HMMA mainloop (BK=64, 2-stage), warp layout 4M x 2N (32x64 per warp)
// — the R10/R11 measured-best configuration.
// =====================================================================
__device__ __forceinline__ void hmma_body(const __nv_bfloat16* __restrict__ A,
                                          const __nv_bfloat16* __restrict__ B,
                                          float acc[2][8][4],
                                          int m0, int n0, int K3,
                                          int kbeg, int klen,
                                          __nv_bfloat16* sm) {
    const int tid = threadIdx.x;
    const int nchunk = klen >> 6;
    const int warp = tid >> 5, lane = tid & 31;
    const int wm = warp & 3, wn = warp >> 2;
    const uint32_t smb = smem_u32(sm);

    auto load_stage = [&](int cc, int s) {
        const uint32_t ab = smb + s * HSTAGE;
        const uint32_t bb = ab + HOPER;
        const int k0 = kbeg + cc * 64;
#pragma unroll
        for (int i = 0; i < 4; i++) {
            int idx = tid + i * 256;
            int row = idx >> 3, cg = idx & 7;
            cp_async16(ab + row * HROW + cg * 16, A + (size_t)(m0 + row) * K3 + k0 + cg * 8);
            cp_async16(bb + row * HROW + cg * 16, B + (size_t)(n0 + row) * K3 + k0 + cg * 8);
        }
        cp_commit();
    };

    load_stage(0, 0);
    load_stage(1, 1);

    const int lrow = lane & 15;
    const int lcol = (lane >> 4) << 3;

    for (int c = 0; c < nchunk; c++) {
        cp_wait<1>();
        __syncthreads();
        const uint32_t ab = smb + (c & 1) * HSTAGE;
        const uint32_t bb = ab + HOPER;
#pragma unroll
        for (int ks = 0; ks < 4; ks++) {
            const uint32_t coff = (ks * 16 + lcol) * 2;
            uint32_t a[2][4], b[8][2];
#pragma unroll
            for (int mt = 0; mt < 2; mt++)
                ldmx4(a[mt][0], a[mt][1], a[mt][2], a[mt][3],
                      ab + (uint32_t)(wm * 32 + mt * 16 + lrow) * HROW + coff);
#pragma unroll
            for (int bp = 0; bp < 4; bp++) {
                uint32_t r0, r1, r2, r3;
                ldmx4(r0, r1, r2, r3,
                      bb + (uint32_t)(wn * 64 + bp * 16 + lrow) * HROW + coff);
                b[bp * 2][0] = r0; b[bp * 2][1] = r2;
                b[bp * 2 + 1][0] = r1; b[bp * 2 + 1][1] = r3;
            }
#pragma unroll
            for (int mt = 0; mt < 2; mt++)
#pragma unroll
                for (int nt = 0; nt < 8; nt++) mma_bf16(acc[mt][nt], a[mt], b[nt]);
        }
        __syncthreads();
        if (c + 2 < nchunk) load_stage(c + 2, c & 1);
    }
}

__device__ __forceinline__ void hmma_epi(float acc[2][8][4], float* C, int m0, int ncol0) {
    const int lane = threadIdx.x & 31, warp = threadIdx.x >> 5;
    const int wm = warp & 3, wn = warp >> 2;
    const int erow = lane >> 2, ecol = (lane & 3) * 2;
#pragma unroll
    for (int mt = 0; mt < 2; mt++) {
        const int r0 = m0 + wm * 32 + mt * 16 + erow;
#pragma unroll
        for (int nt = 0; nt < 8; nt++) {
            const int cc = ncol0 + wn * 64 + nt * 8 + ecol;
            *(float2*)&C[(size_t)r0 * 1024 + cc] = make_float2(acc[mt][nt][0], acc[mt][nt][1]);
            *(float2*)&C[(size_t)(r0 + 8) * 1024 + cc] = make_float2(acc[mt][nt][2], acc[mt][nt][3]);
        }
    }
}

template<bool CAUSAL>
__global__ void __launch_bounds__(256, 2) hmma_gemmz(const __nv_bfloat16* __restrict__ A,
                                                     const __nv_bfloat16* __restrict__ B,
                                                     float* __restrict__ C0,
                                                     float* __restrict__ C1, int K3) {
    extern __shared__ __nv_bfloat16 sm[];
    float acc[2][8][4];
#pragma unroll
    for (int i = 0; i < 2; i++)
#pragma unroll
        for (int j = 0; j < 8; j++)
#pragma unroll
            for (int t = 0; t < 4; t++) acc[i][j][t] = 0.f;
    const int m0 = blockIdx.y * 128, n0 = blockIdx.x * 128;
    const int kc = CAUSAL ? ((m0 + 128) * 3 < K3 ? (m0 + 128) * 3 : K3) : K3;
    const int half = kc >> 1;
    hmma_body(A, B, acc, m0, n0, K3, blockIdx.z * half, half, sm);
    hmma_epi(acc, blockIdx.z ? C1 : C0, m0, n0);
}

__global__ void __launch_bounds__(256, 2) hmma_gemm5(const __nv_bfloat16* __restrict__ A,
                                                     const __nv_bfloat16* __restrict__ B,
                                                     Out5 outs, int K3) {
    extern __shared__ __nv_bfloat16 sm[];
    float acc[2][8][4];
#pragma unroll
    for (int i = 0; i < 2; i++)
#pragma unroll
        for (int j = 0; j < 8; j++)
#pragma unroll
            for (int t = 0; t < 4; t++) acc[i][j][t] = 0.f;
    const int m0 = blockIdx.y * 128, n0 = blockIdx.x * 128;
    hmma_body(A, B, acc, m0, n0, K3, 0, K3, sm);
    hmma_epi(acc, outs.p[blockIdx.x >> 3], m0, (blockIdx.x & 7) * 128);
}

// =====================================================================
// flash pre-split conversions
// =====================================================================
__global__ void convQK3(const float* __restrict__ q, const float* __restrict__ k,
                        __nv_bfloat16* __restrict__ q3, __nv_bfloat16* __restrict__ k3) {
    const int idx = blockIdx.x * 256 + threadIdx.x;
    const int t = idx >> 10, hd = idx & 1023;
    const int h = hd >> 6, d = hd & 63;
    const size_t orow = ((size_t)h * TT + t) * 192;
    const float QSCALE = 0.125f * LOG2E;
    float qv = q[idx] * QSCALE;
    __nv_bfloat16 qhi = __float2bfloat16(qv);
    __nv_bfloat16 qlo = __float2bfloat16(qv - __bfloat162float(qhi));
    q3[orow + d] = qhi; q3[orow + 64 + d] = qlo; q3[orow + 128 + d] = qhi;
    float kv = k[idx];
    __nv_bfloat16 khi = __float2bfloat16(kv);
    __nv_bfloat16 klo = __float2bfloat16(kv - __bfloat162float(khi));
    k3[orow + d] = khi; k3[orow + 64 + d] = khi; k3[orow + 128 + d] = klo;
}

__global__ void convV3T(const float* __restrict__ v, __nv_bfloat16* __restrict__ v3) {
    __shared__ float t[64][65];
    const int kt = blockIdx.x, h = blockIdx.y;
    const int tid = threadIdx.x;
    for (int i = tid; i < 4096; i += 256) {
        int key = i >> 6, d = i & 63;
        t[d][key] = v[(size_t)(kt * 64 + key) * HD + h * 64 + d];
    }
    __syncthreads();
    for (int i = tid; i < 4096; i += 256) {
        int d = i >> 6, j = i & 63;
        float x = t[d][j];
        __nv_bfloat16 hi = __float2bfloat16(x);
        __nv_bfloat16 lo = __float2bfloat16(x - __bfloat162float(hi));
        __nv_bfloat16* base = v3 + ((size_t)h * 64 + d) * 6144 + kt * 192;
        base[j] = hi; base[64 + j] = hi; base[128 + j] = lo;
    }
}

// =====================================================================
// branch 1: flash attention, Q tile 128 rows, cp.async pre-split loads
// =====================================================================
#define FL3_SMEM ((128 + 64 + 64) * 400)

__global__ void __launch_bounds__(256) flash_hmma3(const __nv_bfloat16* __restrict__ q3,
                                                   const __nv_bfloat16* __restrict__ k3,
                                                   const __nv_bfloat16* __restrict__ v3,
                                                   float* __restrict__ out) {
    extern __shared__ __nv_bfloat16 fsm[];
    const int h = blockIdx.y, m0 = blockIdx.x * 128;
    const int tid = threadIdx.x, warp = tid >> 5, lane = tid & 31;
    const uint32_t smb = smem_u32(fsm);
    const uint32_t Qb = smb;
    const uint32_t Kb = smb + 128 * 400;
    const uint32_t Vb = Kb + 64 * 400;
    const int lrow = lane & 15, lcol = (lane >> 4) << 3;

    const __nv_bfloat16* qbase = q3 + ((size_t)h * TT + m0) * 192;
#pragma unroll
    for (int i = 0; i < 12; i++) {
        int c = tid + i * 256;
        int row = c / 24, cg = c % 24;
        cp_async16(Qb + row * 400 + cg * 16, qbase + (size_t)row * 192 + cg * 8);
    }
    cp_commit();

    float m_lo = -1e30f, m_hi = -1e30f, l_lo = 0.f, l_hi = 0.f;
    float O[8][4];
#pragma unroll
    for (int nt = 0; nt < 8; nt++)
#pragma unroll
        for (int t = 0; t < 4; t++) O[nt][t] = 0.f;

    for (int n0 = 0; n0 <= m0 + 64; n0 += 64) {
        __syncthreads();
        const __nv_bfloat16* kbase = k3 + ((size_t)h * TT + n0) * 192;
        const __nv_bfloat16* vbase = v3 + (size_t)h * 64 * 6144 + (n0 >> 6) * 192;
#pragma unroll
        for (int i = 0; i < 6; i++) {
            int c = tid + i * 256;
            int row = c / 24, cg = c % 24;
            cp_async16(Kb + row * 400 + cg * 16, kbase + (size_t)row * 192 + cg * 8);
            cp_async16(Vb + row * 400 + cg * 16, vbase + (size_t)row * 6144 + cg * 8);
        }
        cp_commit();
        cp_wait<0>();
        __syncthreads();

        float s[8][4];
#pragma unroll
        for (int nt = 0; nt < 8; nt++)
#pragma unroll
            for (int t = 0; t < 4; t++) s[nt][t] = 0.f;
#pragma unroll
        for (int ks = 0; ks < 12; ks++) {
            const uint32_t coff = (ks * 16 + lcol) * 2;
            uint32_t a[4], b[8][2];
            ldmx4(a[0], a[1], a[2], a[3], Qb + (uint32_t)(warp * 16 + lrow) * 400 + coff);
#pragma unroll
            for (int bp = 0; bp < 4; bp++) {
                uint32_t r0, r1, r2, r3;
                ldmx4(r0, r1, r2, r3, Kb + (uint32_t)(bp * 16 + lrow) * 400 + coff);
                b[bp * 2][0] = r0; b[bp * 2][1] = r2;
                b[bp * 2 + 1][0] = r1; b[bp * 2 + 1][1] = r3;
            }
#pragma unroll
            for (int nt = 0; nt < 8; nt++) mma_bf16(s[nt], a, b[nt]);
        }

        if (n0 >= m0) {
            const int rl = m0 + warp * 16 + (lane >> 2);
            const int cb = n0 + (lane & 3) * 2;
#pragma unroll
            for (int nt = 0; nt < 8; nt++) {
                int c0 = cb + nt * 8, c1 = c0 + 1;
                if (c0 > rl) s[nt][0] = -1e30f;
                if (c1 > rl) s[nt][1] = -1e30f;
                if (c0 > rl + 8) s[nt][2] = -1e30f;
                if (c1 > rl + 8) s[nt][3] = -1e30f;
            }
        }

        float rmx_lo = -1e30f, rmx_hi = -1e30f;
#pragma unroll
        for (int nt = 0; nt < 8; nt++) {
            rmx_lo = fmaxf(rmx_lo, fmaxf(s[nt][0], s[nt][1]));
            rmx_hi = fmaxf(rmx_hi, fmaxf(s[nt][2], s[nt][3]));
        }
#pragma unroll
        for (int o = 1; o < 4; o <<= 1) {
            rmx_lo = fmaxf(rmx_lo, __shfl_xor_sync(0xffffffffu, rmx_lo, o));
            rmx_hi = fmaxf(rmx_hi, __shfl_xor_sync(0xffffffffu, rmx_hi, o));
        }
        float mn_lo = fmaxf(m_lo, rmx_lo), mn_hi = fmaxf(m_hi, rmx_hi);
        float corr_lo = exp2f(m_lo - mn_lo), corr_hi = exp2f(m_hi - mn_hi);
        m_lo = mn_lo; m_hi = mn_hi;
        float rs_lo = 0.f, rs_hi = 0.f;
#pragma unroll
        for (int nt = 0; nt < 8; nt++) {
            s[nt][0] = exp2f(s[nt][0] - mn_lo); rs_lo += s[nt][0];
            s[nt][1] = exp2f(s[nt][1] - mn_lo); rs_lo += s[nt][1];
            s[nt][2] = exp2f(s[nt][2] - mn_hi); rs_hi += s[nt][2];
            s[nt][3] = exp2f(s[nt][3] - mn_hi); rs_hi += s[nt][3];
        }
#pragma unroll
        for (int o = 1; o < 4; o <<= 1) {
            rs_lo += __shfl_xor_sync(0xffffffffu, rs_lo, o);
            rs_hi += __shfl_xor_sync(0xffffffffu, rs_hi, o);
        }
        l_lo = l_lo * corr_lo + rs_lo;
        l_hi = l_hi * corr_hi + rs_hi;
#pragma unroll
        for (int nt = 0; nt < 8; nt++) {
            O[nt][0] *= corr_lo; O[nt][1] *= corr_lo;
            O[nt][2] *= corr_hi; O[nt][3] *= corr_hi;
        }

        uint32_t phi[4][4], plo[4][4];
#pragma unroll
        for (int kk = 0; kk < 4; kk++) {
            const int n0t = 2 * kk, n1t = 2 * kk + 1;
            __nv_bfloat16 h00 = __float2bfloat16(s[n0t][0]);
            __nv_bfloat16 h01 = __float2bfloat16(s[n0t][1]);
            __nv_bfloat16 h02 = __float2bfloat16(s[n0t][2]);
            __nv_bfloat16 h03 = __float2bfloat16(s[n0t][3]);
            __nv_bfloat16 h10 = __float2bfloat16(s[n1t][0]);
            __nv_bfloat16 h11 = __float2bfloat16(s[n1t][1]);
            __nv_bfloat16 h12 = __float2bfloat16(s[n1t][2]);
            __nv_bfloat16 h13 = __float2bfloat16(s[n1t][3]);
            phi[kk][0] = pack2(h00, h01);
            phi[kk][1] = pack2(h02, h03);
            phi[kk][2] = pack2(h10, h11);
            phi[kk][3] = pack2(h12, h13);
            plo[kk][0] = pack2(__float2bfloat16(s[n0t][0] - __bfloat162float(h00)),
                               __float2bfloat16(s[n0t][1] - __bfloat162float(h01)));
            plo[kk][1] = pack2(__float2bfloat16(s[n0t][2] - __bfloat162float(h02)),
                               __float2bfloat16(s[n0t][3] - __bfloat162float(h03)));
            plo[kk][2] = pack2(__float2bfloat16(s[n1t][0] - __bfloat162float(h10)),
                               __float2bfloat16(s[n1t][1] - __bfloat162float(h11)));
            plo[kk][3] = pack2(__float2bfloat16(s[n1t][2] - __bfloat162float(h12)),
                               __float2bfloat16(s[n1t][3] - __bfloat162float(h13)));
        }

#pragma unroll
        for (int ks = 0; ks < 12; ks++) {
            const uint32_t* a = (ks < 4) ? phi[ks] : (ks < 8) ? plo[ks - 4] : phi[ks - 8];
            const uint32_t coff = (ks * 16 + lcol) * 2;
            uint32_t b[8][2];
#pragma unroll
            for (int bp = 0; bp < 4; bp++) {
                uint32_t r0, r1, r2, r3;
                ldmx4(r0, r1, r2, r3, Vb + (uint32_t)(bp * 16 + lrow) * 400 + coff);
                b[bp * 2][0] = r0; b[bp * 2][1] = r2;
                b[bp * 2 + 1][0] = r1; b[bp * 2 + 1][1] = r3;
            }
#pragma unroll
            for (int nt = 0; nt < 8; nt++) mma_bf16(O[nt], a, b[nt]);
        }
    }

    const float inv_lo = 1.f / l_lo, inv_hi = 1.f / l_hi;
    const int rl = m0 + warp * 16 + (lane >> 2);
#pragma unroll
    for (int nt = 0; nt < 8; nt++) {
        const int col = h * 64 + nt * 8 + (lane & 3) * 2;
        *(float2*)&out[(size_t)rl * HD + col] = make_float2(O[nt][0] * inv_lo, O[nt][1] * inv_lo);
        *(float2*)&out[(size_t)(rl + 8) * HD + col] = make_float2(O[nt][2] * inv_hi, O[nt][3] * inv_hi);
    }
}

// =====================================================================
// conversions (weights, x, echo)
// =====================================================================
__global__ void conv3w6(Src6 src, __nv_bfloat16* __restrict__ D) {
    const int w = blockIdx.y;
    const int idx = blockIdx.x * 256 + threadIdx.x;
    const int m = idx >> 10, k = idx & 1023;
    float x = src.s[w][idx];
    __nv_bfloat16 hi = __float2bfloat16(x);
    __nv_bfloat16 lo = __float2bfloat16(x - __bfloat162float(hi));
    __nv_bfloat16* row = D + (size_t)(w * 1024 + m) * 3072;
    row[k] = hi;
    row[1024 + k] = hi;
    row[2048 + k] = lo;
}

template<bool APAT>
__global__ void conv3(const float* __restrict__ S, __nv_bfloat16* __restrict__ D, int K) {
    const int idx = blockIdx.x * 256 + threadIdx.x;
    const int m = idx / K, k = idx - m * K;
    float x = S[idx];
    __nv_bfloat16 hi = __float2bfloat16(x);
    __nv_bfloat16 lo = __float2bfloat16(x - __bfloat162float(hi));
    const size_t ro = (size_t)m * 3 * K;
    D[ro + k] = hi;
    D[ro + K + k] = APAT ? lo : hi;
    D[ro + 2 * K + k] = APAT ? hi : lo;
}

__global__ void conv3Tg(const float* __restrict__ S, __nv_bfloat16* __restrict__ D,
                        int K, int N) {
    __shared__ float t[32][33];
    const int k0 = blockIdx.x * 32, n0 = blockIdx.y * 32;
    const int tx = threadIdx.x & 31, ty = threadIdx.x >> 5;
    for (int i = ty; i < 32; i += 8) t[i][tx] = S[(size_t)(k0 + i) * N + n0 + tx];
    __syncthreads();
    const int K3 = 3 * K;
    for (int i = ty; i < 32; i += 8) {
        const int n = n0 + i, k = k0 + tx;
        const int g = k >> 6, j = k & 63;
        float x = t[tx][i];
        __nv_bfloat16 hi = __float2bfloat16(x);
        __nv_bfloat16 lo = __float2bfloat16(x - __bfloat162float(hi));
        __nv_bfloat16* base = D + (size_t)n * K3 + g * 192;
        base[j] = hi;
        base[64 + j] = hi;
        base[128 + j] = lo;
    }
}

// ---------------- branch 2: two-pass blocked scan ---------------------
__global__ void __launch_bounds__(256) krrp(const float* __restrict__ r,
                                            const float* __restrict__ rv,
                                            float* __restrict__ out) {
    __shared__ float w[2048];
    __shared__ float rl[2048];
    __shared__ float red[256];
    __shared__ float Sg[4][64];
    const int h = blockIdx.x, tid = threadIdx.x;
    const float Cc = 0.125f * LOG2E;
    float vloc[8], lm = -1e30f;
#pragma unroll
    for (int i = 0; i < 8; i++) {
        float vv = r[h * 2048 + tid * 8 + i] * Cc;
        vloc[i] = vv;
        lm = fmaxf(lm, vv);
    }
    red[tid] = lm; __syncthreads();
    for (int s = 128; s; s >>= 1) { if (tid < s) red[tid] = fmaxf(red[tid], red[tid + s]); __syncthreads(); }
    float M = red[0];
    __syncthreads();
    float run = 0.f, pre[8];
#pragma unroll
    for (int i = 0; i < 8; i++) {
        float e = exp2f(vloc[i] - M);
        w[tid * 8 + i] = e;
        run += e;
        pre[i] = run;
    }
    red[tid] = run; __syncthreads();
    for (int s = 1; s < 256; s <<= 1) {
        float t = (tid >= s) ? red[tid - s] : 0.f;
        __syncthreads();
        red[tid] += t;
        __syncthreads();
    }
    float excl = red[tid] - run;
#pragma unroll
    for (int i = 0; i < 8; i++) rl[tid * 8 + i] = 1.f / (excl + pre[i]);
    __syncthreads();

    const int g = tid >> 6, d = tid & 63;
    const int t0 = g * 512, t1 = t0 + 512;
    const float* rp = rv + h * 64 + d;
    float s1 = 0.f;
#pragma unroll 4
    for (int t = t0; t < t1; t++) s1 += w[t] * rp[(size_t)t * 1024];
    Sg[g][d] = s1;
    __syncthreads();
    float base = 0.f;
#pragma unroll
    for (int gg = 0; gg < 3; gg++)
        if (gg < g) base += Sg[gg][d];
    float acc = base;
    float* op = out + h * 64 + d;
#pragma unroll 4
    for (int t = t0; t < t1; t++) {
        acc += w[t] * rp[(size_t)t * 1024];
        op[(size_t)t * 1024] = acc * rl[t];
    }
}

// ---------------- branch 3 probabilities -> grouped split bf16 -------
__global__ void __launch_bounds__(256) kjp3(const float* __restrict__ sc,
                                            __nv_bfloat16* __restrict__ P3) {
    __shared__ float sk[2048];
    __shared__ float se[2048];
    __shared__ float red[256];
    const int qq = blockIdx.x, tid = threadIdx.x;
    for (int t = tid; t < 2048; t += 256) sk[t] = sc[t];
    __syncthreads();
    const float sq = sk[qq] * LOG2E;
    float lm = -1e30f;
    for (int t = tid; t <= qq; t += 256) lm = fmaxf(lm, sq * sk[t]);
    red[tid] = lm; __syncthreads();
    for (int s = 128; s; s >>= 1) { if (tid < s) red[tid] = fmaxf(red[tid], red[tid + s]); __syncthreads(); }
    float M = red[0];
    __syncthreads();
    float ls = 0.f;
    for (int t = tid; t <= qq; t += 256) {
        float e = exp2f(sq * sk[t] - M);
        se[t] = e;
        ls += e;
    }
    red[tid] = ls; __syncthreads();
    for (int s = 128; s; s >>= 1) { if (tid < s) red[tid] += red[tid + s]; __syncthreads(); }
    const float rinv = 1.f / red[0];
    __nv_bfloat16* Prow = P3 + (size_t)qq * 6144;
    for (int t = tid; t < 2048; t += 256) {
        float p = (t <= qq) ? se[t] * rinv : 0.f;
        __nv_bfloat16 hi = __float2bfloat16(p);
        __nv_bfloat16 lo = __float2bfloat16(p - __bfloat162float(hi));
        const int g = t >> 6, j = t & 63;
        __nv_bfloat16* base = Prow + g * 192;
        base[j] = hi;
        base[64 + j] = lo;
        base[128 + j] = hi;
    }
}

// ---------------- r[h,t] ----------------------------------------------
__global__ void kr(const float* __restrict__ x, const float* __restrict__ wr,
                   float* __restrict__ r) {
    const int h = blockIdx.y;
    const int t = blockIdx.x * 128 + threadIdx.x;
    const float* wp = wr + (size_t)h * EE * TT + t;
    const float* xp = x + (size_t)t * EE;
    float acc = 0.f;
#pragma unroll 8
    for (int e = 0; e < EE; e++) acc += xp[e] * wp[(size_t)e * TT];
    r[h * TT + t] = acc;
}

// ---------------- scores[t] = ||echo[t]||^2 / 32 ----------------------
__global__ void kscores2(const float* __restrict__ echo, float* __restrict__ sc) {
    const int t = blockIdx.x * 8 + (threadIdx.x >> 5);
    const int lane = threadIdx.x & 31;
    const float* ep = echo + (size_t)t * EE;
    float a = 0.f;
#pragma unroll 4
    for (int e = lane * 4; e < EE; e += 128) {
        float4 v = *(const float4*)(ep + e);
        a += v.x * v.x + v.y * v.y + v.z * v.z + v.w * v.w;
    }
#pragma unroll
    for (int o = 16; o > 0; o >>= 1) a += __shfl_xor_sync(0xffffffffu, a, o);
    if (lane == 0) sc[t] = a * (1.f / 32.f);
}

// ---------------- gated combine (o3 = a + b) -> split bf16 ------------
__global__ void kcombine3(const float* __restrict__ o1, const float* __restrict__ o2,
                          const float* __restrict__ o3a, const float* __restrict__ o3b,
                          const float* __restrict__ gate,
                          __nv_bfloat16* __restrict__ comb3) {
    const int idx = blockIdx.x * 256 + threadIdx.x;
    const int c = idx & (HD - 1);
    const int h = c >> 6;
    float g0 = gate[h * 3 + 0], g1 = gate[h * 3 + 1], g2 = gate[h * 3 + 2];
    float mx = fmaxf(g0, fmaxf(g1, g2));
    float e0 = __expf(g0 - mx), e1 = __expf(g1 - mx), e2 = __expf(g2 - mx);
    float inv = 1.f / (e0 + e1 + e2);
    float val = (e0 * o1[idx] + e1 * o2[idx] + e2 * (o3a[idx] + o3b[idx])) * inv;
    __nv_bfloat16 hi = __float2bfloat16(val);
    __nv_bfloat16 lo = __float2bfloat16(val - __bfloat162float(hi));
    const int m = idx >> 10, k = idx & 1023;
    __nv_bfloat16* row = comb3 + (size_t)m * 3072;
    row[k] = hi;
    row[1024 + k] = lo;
    row[2048 + k] = hi;
}

// ---------------- final add ------------------------------------------
__global__ void kadd(const float* __restrict__ a, const float* __restrict__ b,
                     float* __restrict__ out) {
    const int idx = blockIdx.x * 256 + threadIdx.x;
    out[idx] = a[idx] + b[idx];
}

// ---------------- launch: multi-stream fork/join graph -----------------
extern "C" void kernel_launch(void* const* d_in, const int* in_sizes, int n_in,
                              void* d_out, int out_size) {
    const float* x    = (const float*)d_in[0];
    const float* wq   = (const float*)d_in[1];
    const float* wk   = (const float*)d_in[2];
    const float* wv   = (const float*)d_in[3];
    const float* wr   = (const float*)d_in[4];
    const float* wvr  = (const float*)d_in[5];
    const float* wj   = (const float*)d_in[6];
    const float* gate = (const float*)d_in[7];
    const float* wo   = (const float*)d_in[8];
    float* out = (float*)d_out;

    float *q, *k, *v, *rv, *echo, *r, *sc, *o1, *o2, *o3a, *o3b, *f0, *f1;
    __nv_bfloat16 *x3, *w6, *echoT3, *P3, *comb3, *q3f, *k3f, *v3f;
    cudaGetSymbolAddress((void**)&q, g_q);
    cudaGetSymbolAddress((void**)&k, g_k);
    cudaGetSymbolAddress((void**)&v, g_v);
    cudaGetSymbolAddress((void**)&rv, g_rv);
    cudaGetSymbolAddress((void**)&echo, g_echo);
    cudaGetSymbolAddress((void**)&r, g_r);
    cudaGetSymbolAddress((void**)&sc, g_sc);
    cudaGetSymbolAddress((void**)&o1, g_o1);
    cudaGetSymbolAddress((void**)&o2, g_o2);
    cudaGetSymbolAddress((void**)&o3a, g_o3a);
    cudaGetSymbolAddress((void**)&o3b, g_o3b);
    cudaGetSymbolAddress((void**)&f0, g_f0);
    cudaGetSymbolAddress((void**)&f1, g_f1);
    cudaGetSymbolAddress((void**)&x3, g_x3);
    cudaGetSymbolAddress((void**)&w6, g_w6);
    cudaGetSymbolAddress((void**)&echoT3, g_echoT3);
    cudaGetSymbolAddress((void**)&P3, g_P3);
    cudaGetSymbolAddress((void**)&comb3, g_comb3);
    cudaGetSymbolAddress((void**)&q3f, g_q3f);
    cudaGetSymbolAddress((void**)&k3f, g_k3f);
    cudaGetSymbolAddress((void**)&v3f, g_v3f);

    static cudaStream_t sB = nullptr, sC = nullptr;
    static cudaEvent_t evFork, evProj, evO1, evO2, evT;
    if (!sB) {
        cudaStreamCreateWithFlags(&sB, cudaStreamNonBlocking);
        cudaStreamCreateWithFlags(&sC, cudaStreamNonBlocking);
        cudaEventCreateWithFlags(&evFork, cudaEventDisableTiming);
        cudaEventCreateWithFlags(&evProj, cudaEventDisableTiming);
        cudaEventCreateWithFlags(&evO1, cudaEventDisableTiming);
        cudaEventCreateWithFlags(&evO2, cudaEventDisableTiming);
        cudaEventCreateWithFlags(&evT, cudaEventDisableTiming);
        cudaFuncSetAttribute(hmma_gemmz<false>, cudaFuncAttributeMaxDynamicSharedMemorySize, HMMA_SMEM);
        cudaFuncSetAttribute(hmma_gemmz<true>, cudaFuncAttributeMaxDynamicSharedMemorySize, HMMA_SMEM);
        cudaFuncSetAttribute(hmma_gemm5, cudaFuncAttributeMaxDynamicSharedMemorySize, HMMA_SMEM);
        cudaFuncSetAttribute(flash_hmma3, cudaFuncAttributeMaxDynamicSharedMemorySize, FL3_SMEM);
    }

    const int X = 2048 * 1024 / 256;

    // fork: stream C starts kr immediately
    cudaEventRecord(evFork, 0);
    cudaStreamWaitEvent(sC, evFork, 0);
    kr<<<dim3(16, 16), 128, 0, sC>>>(x, wr, r);

    // main: conversions + batched projection
    Src6 src{{wq, wk, wv, wvr, wj, wo}};
    conv3w6<<<dim3(4096, 6), 256>>>(src, w6);
    conv3<true><<<X, 256>>>(x, x3, 1024);
    Out5 outs{{q, k, v, rv, echo}};
    hmma_gemm5<<<dim3(40, 16), 256, HMMA_SMEM>>>(x3, w6, outs, 3072);
    cudaEventRecord(evProj, 0);

    // stream B: echo transpose, flash pre-split, flash
    cudaStreamWaitEvent(sB, evProj, 0);
    conv3Tg<<<dim3(64, 32), 256, 0, sB>>>(echo, echoT3, 2048, 1024);
    cudaEventRecord(evT, sB);
    convQK3<<<X, 256, 0, sB>>>(q, k, q3f, k3f);
    convV3T<<<dim3(32, 16), 256, 0, sB>>>(v, v3f);
    flash_hmma3<<<dim3(16, 16), 256, FL3_SMEM, sB>>>(q3f, k3f, v3f, o1);
    cudaEventRecord(evO1, sB);

    // stream C: krrp
    cudaStreamWaitEvent(sC, evProj, 0);
    krrp<<<16, 256, 0, sC>>>(r, rv, o2);
    cudaEventRecord(evO2, sC);

    // main: janus chain + split-K causal GEMM
    kscores2<<<TT / 8, 256>>>(echo, sc);
    kjp3<<<TT, 256>>>(sc, P3);
    cudaStreamWaitEvent(0, evT, 0);
    hmma_gemmz<true><<<dim3(8, 16, 2), 256, HMMA_SMEM>>>(P3, echoT3, o3a, o3b, 6144);

    // join + combine + split-K output projection
    cudaStreamWaitEvent(0, evO1, 0);
    cudaStreamWaitEvent(0, evO2, 0);
    kcombine3<<<(TT * HD) / 256, 256>>>(o1, o2, o3a, o3b, gate, comb3);
    hmma_gemmz<false><<<dim3(8, 16, 2), 256, HMMA_SMEM>>>(comb3, w6 + (size_t)5 * 1024 * 3072,
                                                          f0, f1, 3072);
    kadd<<<(TT * HD) / 256, 256>>>(f0, f1, out);
}